// round 14
// baseline (speedup 1.0000x reference)
#include <cuda_runtime.h>
#include <cuda_fp16.h>
#include <cstddef>

// Problem dims
constexpr int B_   = 2;
constexpr int SEQ  = 2048;
constexpr int DM   = 1024;   // d_model
constexpr int NH   = 16;     // heads
constexpr int DH   = 64;     // d_head
constexpr int MROWS = B_ * SEQ;          // 4096
constexpr size_t QKV_ELEMS = (size_t)B_ * NH * SEQ * DH;  // 4,194,304

// Scratch (device globals; no runtime allocation)
__device__ __half g_x [(size_t)MROWS * DM];   // x fp16 [m][k]
__device__ __half g_wq[(size_t)DM * DM];      // W_Q transposed [n=c][k=d]
__device__ __half g_wk[(size_t)DM * DM];
__device__ __half g_wv[(size_t)DM * DM];
__device__ __half g_wo[(size_t)DM * DM];      // W_O transposed [n=d][k=c]
__device__ __half g_q [QKV_ELEMS];            // [b,h,s,e], pre-scaled
__device__ __half g_k [QKV_ELEMS];            // [b,h,s,e]
__device__ __half g_v [QKV_ELEMS];            // TRANSPOSED [b,h,e,s]
__device__ __half g_z [QKV_ELEMS];            // [b,s,h,e] == [m][k]

constexpr float QSCALE = 0.125f * 1.44269504089f;  // log2(e)/sqrt(64)

// ---------------------------------------------------------------------------
// helpers
// ---------------------------------------------------------------------------
__device__ __forceinline__ unsigned pack_h2(float lo, float hi) {
    unsigned d;
    asm("cvt.rn.f16x2.f32 %0, %1, %2;" : "=r"(d) : "f"(hi), "f"(lo));
    return d;
}
__device__ __forceinline__ unsigned ex2h2(unsigned x) {
    unsigned y;
    asm("ex2.approx.f16x2 %0, %1;" : "=r"(y) : "r"(x));
    return y;
}
__device__ __forceinline__ void mma_f16(float* c,
                                        unsigned a0, unsigned a1, unsigned a2, unsigned a3,
                                        unsigned b0, unsigned b1) {
    asm("mma.sync.aligned.m16n8k16.row.col.f32.f16.f16.f32 "
        "{%0,%1,%2,%3}, {%4,%5,%6,%7}, {%8,%9}, {%0,%1,%2,%3};"
        : "+f"(c[0]), "+f"(c[1]), "+f"(c[2]), "+f"(c[3])
        : "r"(a0), "r"(a1), "r"(a2), "r"(a3), "r"(b0), "r"(b1));
}
__device__ __forceinline__ void mma_f16_zero(float* c,
                                             unsigned a0, unsigned a1, unsigned a2, unsigned a3,
                                             unsigned b0, unsigned b1) {
    asm("mma.sync.aligned.m16n8k16.row.col.f32.f16.f16.f32 "
        "{%0,%1,%2,%3}, {%4,%5,%6,%7}, {%8,%9}, {%10,%11,%12,%13};"
        : "=f"(c[0]), "=f"(c[1]), "=f"(c[2]), "=f"(c[3])
        : "r"(a0), "r"(a1), "r"(a2), "r"(a3), "r"(b0), "r"(b1),
          "f"(0.0f), "f"(0.0f), "f"(0.0f), "f"(0.0f));
}
__device__ __forceinline__ unsigned smem_u32(const void* p) {
    return (unsigned)__cvta_generic_to_shared(p);
}
__device__ __forceinline__ void ldsm4(unsigned r[4], const __half* p) {
    unsigned a = smem_u32(p);
    asm volatile("ldmatrix.sync.aligned.m8n8.x4.shared.b16 {%0,%1,%2,%3}, [%4];"
                 : "=r"(r[0]), "=r"(r[1]), "=r"(r[2]), "=r"(r[3]) : "r"(a));
}
__device__ __forceinline__ void cp16(unsigned dst, const void* src) {
    asm volatile("cp.async.cg.shared.global [%0], [%1], 16;" :: "r"(dst), "l"(src));
}
__device__ __forceinline__ void cp_commit() {
    asm volatile("cp.async.commit_group;");
}
template<int N> __device__ __forceinline__ void cp_wait() {
    asm volatile("cp.async.wait_group %0;" :: "n"(N));
}

// ---------------------------------------------------------------------------
// Prologue: fp32 -> fp16 conversions + weight transposes
// ---------------------------------------------------------------------------
__global__ void convert_x_kernel(const float* __restrict__ x) {
    int i = blockIdx.x * blockDim.x + threadIdx.x;    // 1M float4
    float4 v = ((const float4*)x)[i];
    uint2 o;
    o.x = pack_h2(v.x, v.y);
    o.y = pack_h2(v.z, v.w);
    ((uint2*)g_x)[i] = o;
}

__global__ void convert_w_kernel(const float* __restrict__ Wq,
                                 const float* __restrict__ Wk,
                                 const float* __restrict__ Wv,
                                 const float* __restrict__ Wo) {
    const int which = blockIdx.y;
    const int idx = blockIdx.x * blockDim.x + threadIdx.x;   // 0..524287
    if (which == 3) {
        int d  = idx & 1023;
        int cp = idx >> 10;       // 0..511
        float f0 = Wo[(size_t)(2 * cp)     * DM + d];
        float f1 = Wo[(size_t)(2 * cp + 1) * DM + d];
        *(unsigned*)&g_wo[(size_t)d * DM + 2 * cp] = pack_h2(f0, f1);
    } else {
        int c  = idx & 1023;
        int dp = idx >> 10;       // 0..511
        const float* W = (which == 0) ? Wq : (which == 1) ? Wk : Wv;
        __half* dst    = (which == 0) ? g_wq : (which == 1) ? g_wk : g_wv;
        int h = c >> 6, e = c & 63;
        float f0 = W[(size_t)h * DM * DH + (size_t)(2 * dp)     * DH + e];
        float f1 = W[(size_t)h * DM * DH + (size_t)(2 * dp + 1) * DH + e];
        *(unsigned*)&dst[(size_t)c * DM + 2 * dp] = pack_h2(f0, f1);
    }
}

// ---------------------------------------------------------------------------
// GEMM geometry: BM=128, BN=128, BK=32 (fp16), 3-stage cp.async, ldmatrix.
// (R7 config — validated fastest)
// ---------------------------------------------------------------------------
constexpr int AS_LD = 40;            // halves per row (32 data + 8 pad)
constexpr int BS_LD = 40;
constexpr int A_ST  = 128 * AS_LD;
constexpr int B_ST  = 128 * BS_LD;
constexpr size_t GEMM_SMEM_BYTES = (size_t)3 * (A_ST + B_ST) * 2;  // 61,440

#define GEMM_ISSUE(Asrc_, Bsrc_, kt_, st_) do {                                   \
    const int kb_ = (kt_) * 32;                                                   \
    __half* Ad_ = As + (st_) * A_ST;                                              \
    __half* Bd_ = Bs + (st_) * B_ST;                                              \
    int r_ = tid >> 1, c_ = (tid & 1) * 16;                                       \
    cp16(smem_u32(Ad_ + r_ * AS_LD + c_),                                         \
         (Asrc_) + (size_t)(m0 + r_) * DM + kb_ + c_);                            \
    cp16(smem_u32(Ad_ + r_ * AS_LD + c_ + 8),                                     \
         (Asrc_) + (size_t)(m0 + r_) * DM + kb_ + c_ + 8);                        \
    cp16(smem_u32(Bd_ + r_ * BS_LD + c_),                                         \
         (Bsrc_) + (size_t)(n0 + r_) * DM + kb_ + c_);                            \
    cp16(smem_u32(Bd_ + r_ * BS_LD + c_ + 8),                                     \
         (Bsrc_) + (size_t)(n0 + r_) * DM + kb_ + c_ + 8);                        \
} while (0)

#define GEMM_COMPUTE(st_) do {                                                    \
    const __half* Asr = As + (st_) * A_ST;                                        \
    const __half* Bsr = Bs + (st_) * B_ST;                                        \
    _Pragma("unroll")                                                             \
    for (int ck = 0; ck < 2; ck++) {                                              \
        unsigned a[4][4];                                                         \
        _Pragma("unroll")                                                         \
        for (int mt = 0; mt < 4; mt++)                                            \
            ldsm4(a[mt], Asr + (wm * 64 + mt * 16 + fa_r) * AS_LD                 \
                          + ck * 16 + fa_h);                                      \
        _Pragma("unroll")                                                         \
        for (int c2 = 0; c2 < 2; c2++) {                                          \
            unsigned bf[4];                                                       \
            ldsm4(bf, Bsr + (wn * 32 + c2 * 16 + fb_r) * BS_LD                    \
                       + ck * 16 + fb_h);                                         \
            _Pragma("unroll")                                                     \
            for (int mt = 0; mt < 4; mt++) {                                      \
                mma_f16(acc[mt][2 * c2],     a[mt][0], a[mt][1], a[mt][2],        \
                        a[mt][3], bf[0], bf[1]);                                  \
                mma_f16(acc[mt][2 * c2 + 1], a[mt][0], a[mt][1], a[mt][2],        \
                        a[mt][3], bf[2], bf[3]);                                  \
            }                                                                     \
        }                                                                         \
    }                                                                             \
} while (0)

// ---------------------------------------------------------------------------
// Kernel 1: fused QKV projection (fp16). Q pre-scaled; V stored transposed.
// ---------------------------------------------------------------------------
__global__ __launch_bounds__(256, 2) void qkv_gemm_tc(
    const float* __restrict__ bq, const float* __restrict__ bk,
    const float* __restrict__ bv)
{
    extern __shared__ __half sg[];
    __half* As = sg;
    __half* Bs = sg + 3 * A_ST;

    const int pz = blockIdx.z;
    const __half* gw  = (pz == 0) ? g_wq : (pz == 1) ? g_wk : g_wv;
    const float* bias = (pz == 0) ? bq : (pz == 1) ? bk : bv;

    const int n0 = blockIdx.x * 128;
    const int m0 = blockIdx.y * 128;
    const int tid  = threadIdx.x;
    const int wid  = tid >> 5;
    const int lane = tid & 31;
    const int wm = wid >> 2;
    const int wn = wid & 3;
    const int g  = lane >> 2;
    const int t  = lane & 3;
    const int fa_r = lane & 15;
    const int fa_h = ((lane >> 4) & 1) * 8;
    const int fb_r = ((lane >> 4) & 1) * 8 + (lane & 7);
    const int fb_h = ((lane >> 3) & 1) * 8;

    float acc[4][4][4] = {};

    GEMM_ISSUE(g_x, gw, 0, 0); cp_commit();
    GEMM_ISSUE(g_x, gw, 1, 1); cp_commit();

    constexpr int NKT = DM / 32;   // 32
    for (int kt = 0; kt < NKT; ++kt) {
        cp_wait<1>();
        __syncthreads();
        if (kt + 2 < NKT) GEMM_ISSUE(g_x, gw, kt + 2, (kt + 2) % 3);
        cp_commit();
        GEMM_COMPUTE(kt % 3);
    }

#pragma unroll
    for (int mt = 0; mt < 4; mt++) {
#pragma unroll
        for (int nt = 0; nt < 4; nt++) {
            int mg = m0 + wm * 64 + mt * 16 + g;
            int c  = n0 + wn * 32 + nt * 8 + t * 2;
            int h  = c >> 6;
            int e  = c & 63;
            float b0 = bias[c], b1 = bias[c + 1];
#pragma unroll
            for (int rr = 0; rr < 2; rr++) {
                int mgr = mg + rr * 8;
                int bb = mgr >> 11;
                int ss = mgr & (SEQ - 1);
                float v0 = acc[mt][nt][rr * 2 + 0] + b0;
                float v1 = acc[mt][nt][rr * 2 + 1] + b1;
                if (pz == 0) {
                    v0 *= QSCALE; v1 *= QSCALE;
                    size_t idx = ((((size_t)bb * NH + h) * SEQ + ss) * DH + e);
                    *(unsigned*)&g_q[idx] = pack_h2(v0, v1);
                } else if (pz == 1) {
                    size_t idx = ((((size_t)bb * NH + h) * SEQ + ss) * DH + e);
                    *(unsigned*)&g_k[idx] = pack_h2(v0, v1);
                } else {
                    size_t base = (((size_t)bb * NH + h) * DH + e) * SEQ + ss;
                    g_v[base]       = __float2half_rn(v0);
                    g_v[base + SEQ] = __float2half_rn(v1);
                }
            }
        }
    }
}

// ---------------------------------------------------------------------------
// Kernel 2: causal flash attention — PAIRED key tiles for 2x ILP per warp.
// 128-thread CTAs (4 warps x 16 q-rows = 64 q rows), 3 CTAs/SM.
// XOR-swizzled K/V/Q (LD=64); 4-stage cp.async; prefetch distance ONE pair:
// pair p+2 is issued into stages (p+2)&3,(p+3)&3 — disjoint from the pair-p
// read stages p&3,(p+1)&3 — with exactly one commit group in flight, so
// cp_wait<0> is exact (fixes the R13 stage-reuse race + wait miscount).
// No max-tracking; P = ex2.f16x2; l via ones-column MMA.
// ---------------------------------------------------------------------------
constexpr int QK_ST = 64 * 64;   // halves per swizzled 64x64 tile
constexpr size_t SMEM_FLASH_BYTES = (size_t)(9 * QK_ST) * 2;  // Q + 4K + 4V = 73,728

// swizzled address (halves): row in [0,64), chunk = 16B unit in [0,8)
#define SWZ(base_, row_, chunk_) ((base_) + (row_) * 64 + (((chunk_) ^ ((row_) & 7)) * 8))

#define FLASH_ISSUE_KV(j_, st_) do {                                             \
    const __half* kp_ = Kg + (size_t)((j_) * 64 + kk) * DH + grp * 32;           \
    const __half* vp_ = Vg + (size_t)kk * SEQ + (j_) * 64 + grp * 32;            \
    __half* kd_ = Ks + (st_) * QK_ST;                                            \
    __half* vd_ = Vt + (st_) * QK_ST;                                            \
    _Pragma("unroll")                                                            \
    for (int i_ = 0; i_ < 4; i_++) {                                             \
        int c_ = grp * 4 + i_;                                                   \
        cp16(smem_u32(SWZ(kd_, kk, c_)), kp_ + i_ * 8);                          \
        cp16(smem_u32(SWZ(vd_, kk, c_)), vp_ + i_ * 8);                          \
    }                                                                            \
} while (0)

// mask sub-tile SC_ at key offset k0_ (diagonal tile)
#define FLASH_MASK(SC_, k0_) do {                                                \
    _Pragma("unroll")                                                            \
    for (int nt = 0; nt < 8; nt++) {                                             \
        _Pragma("unroll")                                                        \
        for (int cc = 0; cc < 2; cc++) {                                         \
            int kg = (k0_) + nt * 8 + t * 2 + cc;                                \
            if (kg > q0 + r0) SC_[nt][cc]     = -3.0e4f;                         \
            if (kg > q0 + r1) SC_[nt][2 + cc] = -3.0e4f;                         \
        }                                                                        \
    }                                                                            \
} while (0)

// PV for one sub-tile: P = ex2h2(pack(s)); O += P V; l via ones column
#define FLASH_PV(SC_, Vst_) do {                                                 \
    _Pragma("unroll")                                                            \
    for (int kc = 0; kc < 4; kc++) {                                             \
        unsigned a0 = ex2h2(pack_h2(SC_[2 * kc][0],     SC_[2 * kc][1]));        \
        unsigned a1 = ex2h2(pack_h2(SC_[2 * kc][2],     SC_[2 * kc][3]));        \
        unsigned a2 = ex2h2(pack_h2(SC_[2 * kc + 1][0], SC_[2 * kc + 1][1]));    \
        unsigned a3 = ex2h2(pack_h2(SC_[2 * kc + 1][2], SC_[2 * kc + 1][3]));    \
        _Pragma("unroll")                                                        \
        for (int c2 = 0; c2 < 4; c2++) {                                         \
            unsigned bf[4];                                                      \
            ldsm4(bf, SWZ((Vst_), c2 * 16 + fb_r, 2 * kc + fb_c));               \
            mma_f16(o[2 * c2],     a0, a1, a2, a3, bf[0], bf[1]);                \
            mma_f16(o[2 * c2 + 1], a0, a1, a2, a3, bf[2], bf[3]);                \
        }                                                                        \
        mma_f16(oL, a0, a1, a2, a3, ones_b, ones_b);                             \
    }                                                                            \
} while (0)

__global__ __launch_bounds__(128, 3) void flash_attn_tc()
{
    extern __shared__ __half smh[];
    __half* Qs = smh;                 // [64x64] swizzled
    __half* Ks = Qs + QK_ST;          // 4 stages, rows=key, cols=e
    __half* Vt = Ks + 4 * QK_ST;      // 4 stages, rows=e, cols=key

    const int bhid  = blockIdx.y;
    const int itile = (gridDim.x - 1) - blockIdx.x;  // heavy q-tiles first
    const int q0    = itile * 64;
    const __half* Qg = g_q + (size_t)bhid * SEQ * DH;
    const __half* Kg = g_k + (size_t)bhid * SEQ * DH;
    const __half* Vg = g_v + (size_t)bhid * DH * SEQ;   // transposed [e][s]

    const int tid  = threadIdx.x;
    const int wid  = tid >> 5;           // 0..3
    const int lane = tid & 31;
    const int g  = lane >> 2;
    const int t  = lane & 3;
    const int r0 = wid * 16 + g;         // local q row (0..63)
    const int r1 = r0 + 8;
    const int kk  = tid & 63;
    const int grp = tid >> 6;            // 0..1
    const int fa_r = lane & 15;
    const int fa_c = (lane >> 4) & 1;
    const int fb_r = ((lane >> 4) & 1) * 8 + (lane & 7);
    const int fb_c = (lane >> 3) & 1;
    const unsigned ones_b = (g == 0) ? 0x3C003C00u : 0u;   // fp16 ones column

    const int jmax = itile;              // key tiles 0..itile

    // prologue: issue pair (0,1) as one group — the ONLY group in flight
    FLASH_ISSUE_KV(0, 0);
    if (1 <= jmax) FLASH_ISSUE_KV(1, 1);
    cp_commit();

    // plain-store Q (fp16, pre-scaled) into swizzled tile
    {
        int q  = tid >> 1;
        const __half* src = Qg + (size_t)(q0 + q) * DH + (tid & 1) * 32;
#pragma unroll
        for (int i = 0; i < 4; i++) {
            int c = (tid & 1) * 4 + i;
            *(uint4*)SWZ(Qs, q, c) = ((const uint4*)src)[i];
        }
    }
    __syncthreads();   // Q visible (plain STS)

    // hoist Q fragments via ldmatrix (swizzled rows)
    unsigned qf[4][4];
#pragma unroll
    for (int ec = 0; ec < 4; ec++)
        ldsm4(qf[ec], SWZ(Qs, wid * 16 + fa_r, 2 * ec + fa_c));

    float o[8][4] = {};
    float oL[4] = {};

    for (int p = 0; p <= jmax; p += 2) {
        cp_wait<0>();            // pair p complete (single group in flight)
        __syncthreads();
        // issue pair p+2 into stages disjoint from the pair-p read stages
        if (p + 2 <= jmax) {
            FLASH_ISSUE_KV(p + 2, (p + 2) & 3);
            if (p + 3 <= jmax) FLASH_ISSUE_KV(p + 3, (p + 3) & 3);
            cp_commit();
        }

        const bool have1 = (p + 1 <= jmax);
        const __half* K0 = Ks + (p & 3) * QK_ST;
        const __half* V0 = Vt + (p & 3) * QK_ST;
        const __half* K1 = Ks + ((p + 1) & 3) * QK_ST;
        const __half* V1 = Vt + ((p + 1) & 3) * QK_ST;

        // ---- Phase A: S for BOTH tiles, interleaved (2x ILP) ----
        float s0[8][4], s1[8][4];
        if (have1) {
#pragma unroll
            for (int ec = 0; ec < 4; ec++) {
#pragma unroll
                for (int c2 = 0; c2 < 4; c2++) {
                    unsigned bf0[4], bf1[4];
                    ldsm4(bf0, SWZ(K0, c2 * 16 + fb_r, 2 * ec + fb_c));
                    ldsm4(bf1, SWZ(K1, c2 * 16 + fb_r, 2 * ec + fb_c));
                    if (ec == 0) {
                        mma_f16_zero(s0[2 * c2],     qf[0][0], qf[0][1], qf[0][2], qf[0][3], bf0[0], bf0[1]);
                        mma_f16_zero(s1[2 * c2],     qf[0][0], qf[0][1], qf[0][2], qf[0][3], bf1[0], bf1[1]);
                        mma_f16_zero(s0[2 * c2 + 1], qf[0][0], qf[0][1], qf[0][2], qf[0][3], bf0[2], bf0[3]);
                        mma_f16_zero(s1[2 * c2 + 1], qf[0][0], qf[0][1], qf[0][2], qf[0][3], bf1[2], bf1[3]);
                    } else {
                        mma_f16(s0[2 * c2],     qf[ec][0], qf[ec][1], qf[ec][2], qf[ec][3], bf0[0], bf0[1]);
                        mma_f16(s1[2 * c2],     qf[ec][0], qf[ec][1], qf[ec][2], qf[ec][3], bf1[0], bf1[1]);
                        mma_f16(s0[2 * c2 + 1], qf[ec][0], qf[ec][1], qf[ec][2], qf[ec][3], bf0[2], bf0[3]);
                        mma_f16(s1[2 * c2 + 1], qf[ec][0], qf[ec][1], qf[ec][2], qf[ec][3], bf1[2], bf1[3]);
                    }
                }
            }
        } else {
#pragma unroll
            for (int ec = 0; ec < 4; ec++) {
#pragma unroll
                for (int c2 = 0; c2 < 4; c2++) {
                    unsigned bf0[4];
                    ldsm4(bf0, SWZ(K0, c2 * 16 + fb_r, 2 * ec + fb_c));
                    if (ec == 0) {
                        mma_f16_zero(s0[2 * c2],     qf[0][0], qf[0][1], qf[0][2], qf[0][3], bf0[0], bf0[1]);
                        mma_f16_zero(s0[2 * c2 + 1], qf[0][0], qf[0][1], qf[0][2], qf[0][3], bf0[2], bf0[3]);
                    } else {
                        mma_f16(s0[2 * c2],     qf[ec][0], qf[ec][1], qf[ec][2], qf[ec][3], bf0[0], bf0[1]);
                        mma_f16(s0[2 * c2 + 1], qf[ec][0], qf[ec][1], qf[ec][2], qf[ec][3], bf0[2], bf0[3]);
                    }
                }
            }
        }

        // ---- mask (diagonal sub-tile only) ----
        if (p == jmax)                FLASH_MASK(s0, p * 64);
        if (have1 && p + 1 == jmax)   FLASH_MASK(s1, (p + 1) * 64);

        // ---- Phase C: PV for both tiles ----
        FLASH_PV(s0, V0);
        if (have1) FLASH_PV(s1, V1);
    }

    // ---- epilogue: z[b, q, h, e] = fp16(o / l), l from ones-column ----
    const int bb = bhid >> 4;
    const int h  = bhid & 15;
    float lr0 = __shfl_sync(0xFFFFFFFFu, oL[0], lane & 0x1C);
    float lr1 = __shfl_sync(0xFFFFFFFFu, oL[2], lane & 0x1C);
    const float li0 = 1.0f / lr0;
    const float li1 = 1.0f / lr1;
#pragma unroll
    for (int nt = 0; nt < 8; nt++) {
        const int e = nt * 8 + t * 2;
        size_t i0 = (((size_t)bb * SEQ + (q0 + r0)) * NH + h) * DH + e;
        size_t i1 = (((size_t)bb * SEQ + (q0 + r1)) * NH + h) * DH + e;
        *(unsigned*)&g_z[i0] = pack_h2(o[nt][0] * li0, o[nt][1] * li0);
        *(unsigned*)&g_z[i1] = pack_h2(o[nt][2] * li1, o[nt][3] * li1);
    }
}

// ---------------------------------------------------------------------------
// Kernel 3: output projection.
// ---------------------------------------------------------------------------
__global__ __launch_bounds__(256, 2) void out_gemm_tc(
    const float* __restrict__ bO, float* __restrict__ out)
{
    extern __shared__ __half sg[];
    __half* As = sg;
    __half* Bs = sg + 3 * A_ST;

    const int n0 = blockIdx.x * 128;
    const int m0 = blockIdx.y * 128;
    const int tid  = threadIdx.x;
    const int wid  = tid >> 5;
    const int lane = tid & 31;
    const int wm = wid >> 2;
    const int wn = wid & 3;
    const int g  = lane >> 2;
    const int t  = lane & 3;
    const int fa_r = lane & 15;
    const int fa_h = ((lane >> 4) & 1) * 8;
    const int fb_r = ((lane >> 4) & 1) * 8 + (lane & 7);
    const int fb_h = ((lane >> 3) & 1) * 8;

    float acc[4][4][4] = {};

    GEMM_ISSUE(g_z, g_wo, 0, 0); cp_commit();
    GEMM_ISSUE(g_z, g_wo, 1, 1); cp_commit();

    constexpr int NKT = DM / 32;   // 32
    for (int kt = 0; kt < NKT; ++kt) {
        cp_wait<1>();
        __syncthreads();
        if (kt + 2 < NKT) GEMM_ISSUE(g_z, g_wo, kt + 2, (kt + 2) % 3);
        cp_commit();
        GEMM_COMPUTE(kt % 3);
    }

#pragma unroll
    for (int mt = 0; mt < 4; mt++) {
#pragma unroll
        for (int nt = 0; nt < 4; nt++) {
            int mg = m0 + wm * 64 + mt * 16 + g;
            int c  = n0 + wn * 32 + nt * 8 + t * 2;
            float b0 = bO[c], b1 = bO[c + 1];
#pragma unroll
            for (int rr = 0; rr < 2; rr++) {
                float2 w;
                w.x = acc[mt][nt][rr * 2 + 0] + b0;
                w.y = acc[mt][nt][rr * 2 + 1] + b1;
                *(float2*)(out + (size_t)(mg + rr * 8) * DM + c) = w;
            }
        }
    }
}

// ---------------------------------------------------------------------------
// Launch
// ---------------------------------------------------------------------------
extern "C" void kernel_launch(void* const* d_in, const int* in_sizes, int n_in,
                              void* d_out, int out_size)
{
    const float* x  = (const float*)d_in[0];
    const float* Wq = (const float*)d_in[1];
    const float* bq = (const float*)d_in[2];
    const float* Wk = (const float*)d_in[3];
    const float* bk = (const float*)d_in[4];
    const float* Wv = (const float*)d_in[5];
    const float* bv = (const float*)d_in[6];
    const float* Wo = (const float*)d_in[7];
    const float* bo = (const float*)d_in[8];
    float* out = (float*)d_out;

    cudaFuncSetAttribute(qkv_gemm_tc,
                         cudaFuncAttributeMaxDynamicSharedMemorySize,
                         (int)GEMM_SMEM_BYTES);
    cudaFuncSetAttribute(out_gemm_tc,
                         cudaFuncAttributeMaxDynamicSharedMemorySize,
                         (int)GEMM_SMEM_BYTES);
    cudaFuncSetAttribute(flash_attn_tc,
                         cudaFuncAttributeMaxDynamicSharedMemorySize,
                         (int)SMEM_FLASH_BYTES);

    convert_x_kernel<<<(MROWS * DM / 4) / 256, 256>>>(x);
    convert_w_kernel<<<dim3((DM * DM / 2) / 256, 4), 256>>>(Wq, Wk, Wv, Wo);

    dim3 g1(DM / 128, MROWS / 128, 3);   // (8, 32, 3)
    qkv_gemm_tc<<<g1, 256, GEMM_SMEM_BYTES>>>(bq, bk, bv);

    dim3 g2(SEQ / 64, B_ * NH);           // (32, 32) — 1024 CTAs of 128 thr
    flash_attn_tc<<<g2, 128, SMEM_FLASH_BYTES>>>();

    dim3 g3(DM / 128, MROWS / 128);       // (8, 32)
    out_gemm_tc<<<g3, 256, GEMM_SMEM_BYTES>>>(bo, out);
}

// round 15
// speedup vs baseline: 1.1368x; 1.1368x over previous
#include <cuda_runtime.h>
#include <cuda_fp16.h>
#include <cstddef>

// Problem dims
constexpr int B_   = 2;
constexpr int SEQ  = 2048;
constexpr int DM   = 1024;   // d_model
constexpr int NH   = 16;     // heads
constexpr int DH   = 64;     // d_head
constexpr int MROWS = B_ * SEQ;          // 4096
constexpr size_t QKV_ELEMS = (size_t)B_ * NH * SEQ * DH;  // 4,194,304

// Scratch (device globals; no runtime allocation)
__device__ __half g_x [(size_t)MROWS * DM];   // x fp16 [m][k]
__device__ __half g_wq[(size_t)DM * DM];      // W_Q transposed [n=c][k=d]
__device__ __half g_wk[(size_t)DM * DM];
__device__ __half g_wv[(size_t)DM * DM];
__device__ __half g_wo[(size_t)DM * DM];      // W_O transposed [n=d][k=c]
__device__ __half g_q [QKV_ELEMS];            // [b,h,s,e], pre-scaled
__device__ __half g_k [QKV_ELEMS];            // [b,h,s,e]
__device__ __half g_v [QKV_ELEMS];            // TRANSPOSED [b,h,e,s]
__device__ __half g_z [QKV_ELEMS];            // [b,s,h,e] == [m][k]

constexpr float QSCALE = 0.125f * 1.44269504089f;  // log2(e)/sqrt(64)

// ---------------------------------------------------------------------------
// helpers
// ---------------------------------------------------------------------------
__device__ __forceinline__ unsigned pack_h2(float lo, float hi) {
    unsigned d;
    asm("cvt.rn.f16x2.f32 %0, %1, %2;" : "=r"(d) : "f"(hi), "f"(lo));
    return d;
}
__device__ __forceinline__ unsigned ex2h2(unsigned x) {
    unsigned y;
    asm("ex2.approx.f16x2 %0, %1;" : "=r"(y) : "r"(x));
    return y;
}
__device__ __forceinline__ void mma_f16(float* c,
                                        unsigned a0, unsigned a1, unsigned a2, unsigned a3,
                                        unsigned b0, unsigned b1) {
    asm("mma.sync.aligned.m16n8k16.row.col.f32.f16.f16.f32 "
        "{%0,%1,%2,%3}, {%4,%5,%6,%7}, {%8,%9}, {%0,%1,%2,%3};"
        : "+f"(c[0]), "+f"(c[1]), "+f"(c[2]), "+f"(c[3])
        : "r"(a0), "r"(a1), "r"(a2), "r"(a3), "r"(b0), "r"(b1));
}
__device__ __forceinline__ void mma_f16_zero(float* c,
                                             unsigned a0, unsigned a1, unsigned a2, unsigned a3,
                                             unsigned b0, unsigned b1) {
    asm("mma.sync.aligned.m16n8k16.row.col.f32.f16.f16.f32 "
        "{%0,%1,%2,%3}, {%4,%5,%6,%7}, {%8,%9}, {%10,%11,%12,%13};"
        : "=f"(c[0]), "=f"(c[1]), "=f"(c[2]), "=f"(c[3])
        : "r"(a0), "r"(a1), "r"(a2), "r"(a3), "r"(b0), "r"(b1),
          "f"(0.0f), "f"(0.0f), "f"(0.0f), "f"(0.0f));
}
__device__ __forceinline__ unsigned smem_u32(const void* p) {
    return (unsigned)__cvta_generic_to_shared(p);
}
__device__ __forceinline__ void ldsm4(unsigned r[4], const __half* p) {
    unsigned a = smem_u32(p);
    asm volatile("ldmatrix.sync.aligned.m8n8.x4.shared.b16 {%0,%1,%2,%3}, [%4];"
                 : "=r"(r[0]), "=r"(r[1]), "=r"(r[2]), "=r"(r[3]) : "r"(a));
}
__device__ __forceinline__ void cp16(unsigned dst, const void* src) {
    asm volatile("cp.async.cg.shared.global [%0], [%1], 16;" :: "r"(dst), "l"(src));
}
__device__ __forceinline__ void cp_commit() {
    asm volatile("cp.async.commit_group;");
}
template<int N> __device__ __forceinline__ void cp_wait() {
    asm volatile("cp.async.wait_group %0;" :: "n"(N));
}

// ---------------------------------------------------------------------------
// Prologue: fp32 -> fp16 conversions. convert_w is a proper tiled transpose
// (32x32 smem tile, pad 33) — coalesced reads AND writes (the old version
// stored one 4B pack per thread at 2KB stride: fully uncoalesced).
// ---------------------------------------------------------------------------
__global__ void convert_x_kernel(const float* __restrict__ x) {
    int i = blockIdx.x * blockDim.x + threadIdx.x;    // 1M float4
    float4 v = ((const float4*)x)[i];
    uint2 o;
    o.x = pack_h2(v.x, v.y);
    o.y = pack_h2(v.z, v.w);
    ((uint2*)g_x)[i] = o;
}

__global__ void convert_w_kernel(const float* __restrict__ Wq,
                                 const float* __restrict__ Wk,
                                 const float* __restrict__ Wv,
                                 const float* __restrict__ Wo) {
    __shared__ float tile[32][33];
    const int z  = blockIdx.z;
    const int tx = threadIdx.x;
    const int ty = threadIdx.y;
    if (z == 3) {
        // g_wo[d][c] = Wo[c][d]  (1024x1024 transpose)
        const int c0 = blockIdx.y * 32;
        const int d0 = blockIdx.x * 32;
#pragma unroll
        for (int k = 0; k < 4; k++) {
            int r = ty + k * 8;
            tile[r][tx] = Wo[(size_t)(c0 + r) * DM + d0 + tx];
        }
        __syncthreads();
#pragma unroll
        for (int k = 0; k < 4; k++) {
            int rr = ty + k * 8;
            g_wo[(size_t)(d0 + rr) * DM + c0 + tx] = __float2half_rn(tile[tx][rr]);
        }
    } else {
        // dst[c][d] = W[h][d][e], c = h*64+e  (per-h 1024x64 transpose)
        const float* W = (z == 0) ? Wq : (z == 1) ? Wk : Wv;
        __half* dst    = (z == 0) ? g_wq : (z == 1) ? g_wk : g_wv;
        const int h  = blockIdx.y >> 1;
        const int e0 = (blockIdx.y & 1) * 32;
        const int d0 = blockIdx.x * 32;
        const float* src = W + (size_t)h * DM * DH;
#pragma unroll
        for (int k = 0; k < 4; k++) {
            int r = ty + k * 8;   // d offset
            tile[r][tx] = src[(size_t)(d0 + r) * DH + e0 + tx];
        }
        __syncthreads();
#pragma unroll
        for (int k = 0; k < 4; k++) {
            int rr = ty + k * 8;  // e offset
            dst[(size_t)(h * DH + e0 + rr) * DM + d0 + tx] = __float2half_rn(tile[tx][rr]);
        }
    }
}

// ---------------------------------------------------------------------------
// GEMM geometry: BM=128, BN=128, BK=32 (fp16), 3-stage cp.async, ldmatrix.
// (R7 config — validated fastest)
// ---------------------------------------------------------------------------
constexpr int AS_LD = 40;            // halves per row (32 data + 8 pad)
constexpr int BS_LD = 40;
constexpr int A_ST  = 128 * AS_LD;
constexpr int B_ST  = 128 * BS_LD;
constexpr size_t GEMM_SMEM_BYTES = (size_t)3 * (A_ST + B_ST) * 2;  // 61,440

#define GEMM_ISSUE(Asrc_, Bsrc_, kt_, st_) do {                                   \
    const int kb_ = (kt_) * 32;                                                   \
    __half* Ad_ = As + (st_) * A_ST;                                              \
    __half* Bd_ = Bs + (st_) * B_ST;                                              \
    int r_ = tid >> 1, c_ = (tid & 1) * 16;                                       \
    cp16(smem_u32(Ad_ + r_ * AS_LD + c_),                                         \
         (Asrc_) + (size_t)(m0 + r_) * DM + kb_ + c_);                            \
    cp16(smem_u32(Ad_ + r_ * AS_LD + c_ + 8),                                     \
         (Asrc_) + (size_t)(m0 + r_) * DM + kb_ + c_ + 8);                        \
    cp16(smem_u32(Bd_ + r_ * BS_LD + c_),                                         \
         (Bsrc_) + (size_t)(n0 + r_) * DM + kb_ + c_);                            \
    cp16(smem_u32(Bd_ + r_ * BS_LD + c_ + 8),                                     \
         (Bsrc_) + (size_t)(n0 + r_) * DM + kb_ + c_ + 8);                        \
} while (0)

#define GEMM_COMPUTE(st_) do {                                                    \
    const __half* Asr = As + (st_) * A_ST;                                        \
    const __half* Bsr = Bs + (st_) * B_ST;                                        \
    _Pragma("unroll")                                                             \
    for (int ck = 0; ck < 2; ck++) {                                              \
        unsigned a[4][4];                                                         \
        _Pragma("unroll")                                                         \
        for (int mt = 0; mt < 4; mt++)                                            \
            ldsm4(a[mt], Asr + (wm * 64 + mt * 16 + fa_r) * AS_LD                 \
                          + ck * 16 + fa_h);                                      \
        _Pragma("unroll")                                                         \
        for (int c2 = 0; c2 < 2; c2++) {                                          \
            unsigned bf[4];                                                       \
            ldsm4(bf, Bsr + (wn * 32 + c2 * 16 + fb_r) * BS_LD                    \
                       + ck * 16 + fb_h);                                         \
            _Pragma("unroll")                                                     \
            for (int mt = 0; mt < 4; mt++) {                                      \
                mma_f16(acc[mt][2 * c2],     a[mt][0], a[mt][1], a[mt][2],        \
                        a[mt][3], bf[0], bf[1]);                                  \
                mma_f16(acc[mt][2 * c2 + 1], a[mt][0], a[mt][1], a[mt][2],        \
                        a[mt][3], bf[2], bf[3]);                                  \
            }                                                                     \
        }                                                                         \
    }                                                                             \
} while (0)

// ---------------------------------------------------------------------------
// Kernel 1: fused QKV projection (fp16). Q pre-scaled; V stored transposed.
// ---------------------------------------------------------------------------
__global__ __launch_bounds__(256, 2) void qkv_gemm_tc(
    const float* __restrict__ bq, const float* __restrict__ bk,
    const float* __restrict__ bv)
{
    extern __shared__ __half sg[];
    __half* As = sg;
    __half* Bs = sg + 3 * A_ST;

    const int pz = blockIdx.z;
    const __half* gw  = (pz == 0) ? g_wq : (pz == 1) ? g_wk : g_wv;
    const float* bias = (pz == 0) ? bq : (pz == 1) ? bk : bv;

    const int n0 = blockIdx.x * 128;
    const int m0 = blockIdx.y * 128;
    const int tid  = threadIdx.x;
    const int wid  = tid >> 5;
    const int lane = tid & 31;
    const int wm = wid >> 2;
    const int wn = wid & 3;
    const int g  = lane >> 2;
    const int t  = lane & 3;
    const int fa_r = lane & 15;
    const int fa_h = ((lane >> 4) & 1) * 8;
    const int fb_r = ((lane >> 4) & 1) * 8 + (lane & 7);
    const int fb_h = ((lane >> 3) & 1) * 8;

    float acc[4][4][4] = {};

    GEMM_ISSUE(g_x, gw, 0, 0); cp_commit();
    GEMM_ISSUE(g_x, gw, 1, 1); cp_commit();

    constexpr int NKT = DM / 32;   // 32
    for (int kt = 0; kt < NKT; ++kt) {
        cp_wait<1>();
        __syncthreads();
        if (kt + 2 < NKT) GEMM_ISSUE(g_x, gw, kt + 2, (kt + 2) % 3);
        cp_commit();
        GEMM_COMPUTE(kt % 3);
    }

#pragma unroll
    for (int mt = 0; mt < 4; mt++) {
#pragma unroll
        for (int nt = 0; nt < 4; nt++) {
            int mg = m0 + wm * 64 + mt * 16 + g;
            int c  = n0 + wn * 32 + nt * 8 + t * 2;
            int h  = c >> 6;
            int e  = c & 63;
            float b0 = bias[c], b1 = bias[c + 1];
#pragma unroll
            for (int rr = 0; rr < 2; rr++) {
                int mgr = mg + rr * 8;
                int bb = mgr >> 11;
                int ss = mgr & (SEQ - 1);
                float v0 = acc[mt][nt][rr * 2 + 0] + b0;
                float v1 = acc[mt][nt][rr * 2 + 1] + b1;
                if (pz == 0) {
                    v0 *= QSCALE; v1 *= QSCALE;
                    size_t idx = ((((size_t)bb * NH + h) * SEQ + ss) * DH + e);
                    *(unsigned*)&g_q[idx] = pack_h2(v0, v1);
                } else if (pz == 1) {
                    size_t idx = ((((size_t)bb * NH + h) * SEQ + ss) * DH + e);
                    *(unsigned*)&g_k[idx] = pack_h2(v0, v1);
                } else {
                    size_t base = (((size_t)bb * NH + h) * DH + e) * SEQ + ss;
                    g_v[base]       = __float2half_rn(v0);
                    g_v[base + SEQ] = __float2half_rn(v1);
                }
            }
        }
    }
}

// ---------------------------------------------------------------------------
// Kernel 2: causal flash attention (R12 config — validated fastest).
// 128-thread CTAs (4 warps x 16 q-rows = 64 q rows), 4 CTAs/SM.
// XOR-swizzled K/V/Q (LD=64); 3-stage cp.async, prefetch distance 2,
// wait_group<1>. Grid TRANSPOSED: bh fastest -> uniform work per wave.
// No max-tracking; P = ex2.f16x2; l via ones-column MMA.
// ---------------------------------------------------------------------------
constexpr int QK_ST = 64 * 64;   // halves per swizzled 64x64 tile
constexpr size_t SMEM_FLASH_BYTES = (size_t)(7 * QK_ST) * 2;  // Q + 3K + 3V = 57,344

// swizzled address (halves): row in [0,64), chunk = 16B unit in [0,8)
#define SWZ(base_, row_, chunk_) ((base_) + (row_) * 64 + (((chunk_) ^ ((row_) & 7)) * 8))

#define FLASH_ISSUE_KV(j_, st_) do {                                             \
    const __half* kp_ = Kg + (size_t)((j_) * 64 + kk) * DH + grp * 32;           \
    const __half* vp_ = Vg + (size_t)kk * SEQ + (j_) * 64 + grp * 32;            \
    __half* kd_ = Ks + (st_) * QK_ST;                                            \
    __half* vd_ = Vt + (st_) * QK_ST;                                            \
    _Pragma("unroll")                                                            \
    for (int i_ = 0; i_ < 4; i_++) {                                             \
        int c_ = grp * 4 + i_;                                                   \
        cp16(smem_u32(SWZ(kd_, kk, c_)), kp_ + i_ * 8);                          \
        cp16(smem_u32(SWZ(vd_, kk, c_)), vp_ + i_ * 8);                          \
    }                                                                            \
} while (0)

__global__ __launch_bounds__(128, 4) void flash_attn_tc()
{
    extern __shared__ __half smh[];
    __half* Qs = smh;                 // [64x64] swizzled
    __half* Ks = Qs + QK_ST;          // 3 stages, rows=key, cols=e
    __half* Vt = Ks + 3 * QK_ST;      // 3 stages, rows=e, cols=key

    const int bhid  = blockIdx.x;                        // bh fastest
    const int itile = (int)(gridDim.y - 1) - blockIdx.y; // heavy q-tiles first
    const int q0    = itile * 64;
    const __half* Qg = g_q + (size_t)bhid * SEQ * DH;
    const __half* Kg = g_k + (size_t)bhid * SEQ * DH;
    const __half* Vg = g_v + (size_t)bhid * DH * SEQ;   // transposed [e][s]

    const int tid  = threadIdx.x;
    const int wid  = tid >> 5;           // 0..3
    const int lane = tid & 31;
    const int g  = lane >> 2;
    const int t  = lane & 3;
    const int r0 = wid * 16 + g;         // local q row (0..63)
    const int r1 = r0 + 8;
    const int kk  = tid & 63;
    const int grp = tid >> 6;            // 0..1
    const int fa_r = lane & 15;
    const int fa_c = (lane >> 4) & 1;
    const int fb_r = ((lane >> 4) & 1) * 8 + (lane & 7);
    const int fb_c = (lane >> 3) & 1;
    const unsigned ones_b = (g == 0) ? 0x3C003C00u : 0u;   // fp16 ones column

    const int jmax = itile;              // key tiles 0..itile

    // prologue: prefetch tiles 0 and 1
    FLASH_ISSUE_KV(0, 0);
    cp_commit();
    if (jmax >= 1) { FLASH_ISSUE_KV(1, 1); cp_commit(); }

    // plain-store Q (fp16, pre-scaled) into swizzled tile
    {
        int q  = tid >> 1;
        const __half* src = Qg + (size_t)(q0 + q) * DH + (tid & 1) * 32;
#pragma unroll
        for (int i = 0; i < 4; i++) {
            int c = (tid & 1) * 4 + i;
            *(uint4*)SWZ(Qs, q, c) = ((const uint4*)src)[i];
        }
    }
    __syncthreads();   // Q visible (plain STS)

    // hoist Q fragments via ldmatrix (swizzled rows)
    unsigned qf[4][4];
#pragma unroll
    for (int ec = 0; ec < 4; ec++)
        ldsm4(qf[ec], SWZ(Qs, wid * 16 + fa_r, 2 * ec + fa_c));

    float o[8][4] = {};
    float oL[4] = {};

    for (int j = 0; j <= jmax; ++j) {
        if (j < jmax) cp_wait<1>(); else cp_wait<0>();
        __syncthreads();
        if (j + 2 <= jmax) { FLASH_ISSUE_KV(j + 2, (j + 2) % 3); cp_commit(); }

        const __half* Kst = Ks + (j % 3) * QK_ST;
        const __half* Vst = Vt + (j % 3) * QK_ST;

        // ---- Phase A: S = Q K^T ----
        float s[8][4];
#pragma unroll
        for (int ec = 0; ec < 4; ec++) {
#pragma unroll
            for (int c2 = 0; c2 < 4; c2++) {
                unsigned bf[4];
                ldsm4(bf, SWZ(Kst, c2 * 16 + fb_r, 2 * ec + fb_c));
                if (ec == 0) {
                    mma_f16_zero(s[2 * c2],     qf[0][0], qf[0][1], qf[0][2],
                                 qf[0][3], bf[0], bf[1]);
                    mma_f16_zero(s[2 * c2 + 1], qf[0][0], qf[0][1], qf[0][2],
                                 qf[0][3], bf[2], bf[3]);
                } else {
                    mma_f16(s[2 * c2],     qf[ec][0], qf[ec][1], qf[ec][2],
                            qf[ec][3], bf[0], bf[1]);
                    mma_f16(s[2 * c2 + 1], qf[ec][0], qf[ec][1], qf[ec][2],
                            qf[ec][3], bf[2], bf[3]);
                }
            }
        }

        // ---- mask (diagonal tile only) ----
        if (j == jmax) {
            const int k0 = j * 64;
#pragma unroll
            for (int nt = 0; nt < 8; nt++) {
#pragma unroll
                for (int cc = 0; cc < 2; cc++) {
                    int kg = k0 + nt * 8 + t * 2 + cc;
                    if (kg > q0 + r0) s[nt][cc]     = -3.0e4f;
                    if (kg > q0 + r1) s[nt][2 + cc] = -3.0e4f;
                }
            }
        }

        // ---- Phase C: P = ex2h2(pack(s)); O += P V; l via ones ----
#pragma unroll
        for (int kc = 0; kc < 4; kc++) {
            unsigned a0 = ex2h2(pack_h2(s[2 * kc][0],     s[2 * kc][1]));
            unsigned a1 = ex2h2(pack_h2(s[2 * kc][2],     s[2 * kc][3]));
            unsigned a2 = ex2h2(pack_h2(s[2 * kc + 1][0], s[2 * kc + 1][1]));
            unsigned a3 = ex2h2(pack_h2(s[2 * kc + 1][2], s[2 * kc + 1][3]));
#pragma unroll
            for (int c2 = 0; c2 < 4; c2++) {
                unsigned bf[4];
                ldsm4(bf, SWZ(Vst, c2 * 16 + fb_r, 2 * kc + fb_c));
                mma_f16(o[2 * c2],     a0, a1, a2, a3, bf[0], bf[1]);
                mma_f16(o[2 * c2 + 1], a0, a1, a2, a3, bf[2], bf[3]);
            }
            mma_f16(oL, a0, a1, a2, a3, ones_b, ones_b);
        }
    }

    // ---- epilogue: z[b, q, h, e] = fp16(o / l), l from ones-column ----
    const int bb = bhid >> 4;
    const int h  = bhid & 15;
    float lr0 = __shfl_sync(0xFFFFFFFFu, oL[0], lane & 0x1C);
    float lr1 = __shfl_sync(0xFFFFFFFFu, oL[2], lane & 0x1C);
    const float li0 = 1.0f / lr0;
    const float li1 = 1.0f / lr1;
#pragma unroll
    for (int nt = 0; nt < 8; nt++) {
        const int e = nt * 8 + t * 2;
        size_t i0 = (((size_t)bb * SEQ + (q0 + r0)) * NH + h) * DH + e;
        size_t i1 = (((size_t)bb * SEQ + (q0 + r1)) * NH + h) * DH + e;
        *(unsigned*)&g_z[i0] = pack_h2(o[nt][0] * li0, o[nt][1] * li0);
        *(unsigned*)&g_z[i1] = pack_h2(o[nt][2] * li1, o[nt][3] * li1);
    }
}

// ---------------------------------------------------------------------------
// Kernel 3: output projection.
// ---------------------------------------------------------------------------
__global__ __launch_bounds__(256, 2) void out_gemm_tc(
    const float* __restrict__ bO, float* __restrict__ out)
{
    extern __shared__ __half sg[];
    __half* As = sg;
    __half* Bs = sg + 3 * A_ST;

    const int n0 = blockIdx.x * 128;
    const int m0 = blockIdx.y * 128;
    const int tid  = threadIdx.x;
    const int wid  = tid >> 5;
    const int lane = tid & 31;
    const int wm = wid >> 2;
    const int wn = wid & 3;
    const int g  = lane >> 2;
    const int t  = lane & 3;
    const int fa_r = lane & 15;
    const int fa_h = ((lane >> 4) & 1) * 8;
    const int fb_r = ((lane >> 4) & 1) * 8 + (lane & 7);
    const int fb_h = ((lane >> 3) & 1) * 8;

    float acc[4][4][4] = {};

    GEMM_ISSUE(g_z, g_wo, 0, 0); cp_commit();
    GEMM_ISSUE(g_z, g_wo, 1, 1); cp_commit();

    constexpr int NKT = DM / 32;   // 32
    for (int kt = 0; kt < NKT; ++kt) {
        cp_wait<1>();
        __syncthreads();
        if (kt + 2 < NKT) GEMM_ISSUE(g_z, g_wo, kt + 2, (kt + 2) % 3);
        cp_commit();
        GEMM_COMPUTE(kt % 3);
    }

#pragma unroll
    for (int mt = 0; mt < 4; mt++) {
#pragma unroll
        for (int nt = 0; nt < 4; nt++) {
            int mg = m0 + wm * 64 + mt * 16 + g;
            int c  = n0 + wn * 32 + nt * 8 + t * 2;
            float b0 = bO[c], b1 = bO[c + 1];
#pragma unroll
            for (int rr = 0; rr < 2; rr++) {
                float2 w;
                w.x = acc[mt][nt][rr * 2 + 0] + b0;
                w.y = acc[mt][nt][rr * 2 + 1] + b1;
                *(float2*)(out + (size_t)(mg + rr * 8) * DM + c) = w;
            }
        }
    }
}

// ---------------------------------------------------------------------------
// Launch
// ---------------------------------------------------------------------------
extern "C" void kernel_launch(void* const* d_in, const int* in_sizes, int n_in,
                              void* d_out, int out_size)
{
    const float* x  = (const float*)d_in[0];
    const float* Wq = (const float*)d_in[1];
    const float* bq = (const float*)d_in[2];
    const float* Wk = (const float*)d_in[3];
    const float* bk = (const float*)d_in[4];
    const float* Wv = (const float*)d_in[5];
    const float* bv = (const float*)d_in[6];
    const float* Wo = (const float*)d_in[7];
    const float* bo = (const float*)d_in[8];
    float* out = (float*)d_out;

    cudaFuncSetAttribute(qkv_gemm_tc,
                         cudaFuncAttributeMaxDynamicSharedMemorySize,
                         (int)GEMM_SMEM_BYTES);
    cudaFuncSetAttribute(out_gemm_tc,
                         cudaFuncAttributeMaxDynamicSharedMemorySize,
                         (int)GEMM_SMEM_BYTES);
    cudaFuncSetAttribute(flash_attn_tc,
                         cudaFuncAttributeMaxDynamicSharedMemorySize,
                         (int)SMEM_FLASH_BYTES);

    convert_x_kernel<<<(MROWS * DM / 4) / 256, 256>>>(x);
    convert_w_kernel<<<dim3(32, 32, 4), dim3(32, 8)>>>(Wq, Wk, Wv, Wo);

    dim3 g1(DM / 128, MROWS / 128, 3);   // (8, 32, 3)
    qkv_gemm_tc<<<g1, 256, GEMM_SMEM_BYTES>>>(bq, bk, bv);

    dim3 g2(B_ * NH, SEQ / 64);           // (32 bh, 32 q-tiles) — bh fastest
    flash_attn_tc<<<g2, 128, SMEM_FLASH_BYTES>>>();

    dim3 g3(DM / 128, MROWS / 128);       // (8, 32)
    out_gemm_tc<<<g3, 256, GEMM_SMEM_BYTES>>>(bo, out);
}

// round 16
// speedup vs baseline: 1.2360x; 1.0873x over previous
#include <cuda_runtime.h>
#include <cuda_fp16.h>
#include <cstddef>

// Problem dims
constexpr int B_   = 2;
constexpr int SEQ  = 2048;
constexpr int DM   = 1024;   // d_model
constexpr int NH   = 16;     // heads
constexpr int DH   = 64;     // d_head
constexpr int MROWS = B_ * SEQ;          // 4096
constexpr size_t QKV_ELEMS = (size_t)B_ * NH * SEQ * DH;  // 4,194,304

// Scratch (device globals; no runtime allocation)
__device__ __half g_x [(size_t)MROWS * DM];   // x fp16 [m][k]
__device__ __half g_wq[(size_t)DM * DM];      // W_Q transposed [n=c][k=d]
__device__ __half g_wk[(size_t)DM * DM];
__device__ __half g_wv[(size_t)DM * DM];
__device__ __half g_wo[(size_t)DM * DM];      // W_O transposed [n=d][k=c]
__device__ __half g_q [QKV_ELEMS];            // [b,h,s,e], pre-scaled
__device__ __half g_k [QKV_ELEMS];            // [b,h,s,e]
__device__ __half g_v [QKV_ELEMS];            // TRANSPOSED [b,h,e,s]
__device__ __half g_z [QKV_ELEMS];            // [b,s,h,e] == [m][k]

constexpr float QSCALE = 0.125f * 1.44269504089f;  // log2(e)/sqrt(64)

// ---------------------------------------------------------------------------
// helpers
// ---------------------------------------------------------------------------
__device__ __forceinline__ unsigned pack_h2(float lo, float hi) {
    unsigned d;
    asm("cvt.rn.f16x2.f32 %0, %1, %2;" : "=r"(d) : "f"(hi), "f"(lo));
    return d;
}
__device__ __forceinline__ unsigned ex2h2(unsigned x) {
    unsigned y;
    asm("ex2.approx.f16x2 %0, %1;" : "=r"(y) : "r"(x));
    return y;
}
__device__ __forceinline__ void mma_f16(float* c,
                                        unsigned a0, unsigned a1, unsigned a2, unsigned a3,
                                        unsigned b0, unsigned b1) {
    asm("mma.sync.aligned.m16n8k16.row.col.f32.f16.f16.f32 "
        "{%0,%1,%2,%3}, {%4,%5,%6,%7}, {%8,%9}, {%0,%1,%2,%3};"
        : "+f"(c[0]), "+f"(c[1]), "+f"(c[2]), "+f"(c[3])
        : "r"(a0), "r"(a1), "r"(a2), "r"(a3), "r"(b0), "r"(b1));
}
__device__ __forceinline__ void mma_f16_zero(float* c,
                                             unsigned a0, unsigned a1, unsigned a2, unsigned a3,
                                             unsigned b0, unsigned b1) {
    asm("mma.sync.aligned.m16n8k16.row.col.f32.f16.f16.f32 "
        "{%0,%1,%2,%3}, {%4,%5,%6,%7}, {%8,%9}, {%10,%11,%12,%13};"
        : "=f"(c[0]), "=f"(c[1]), "=f"(c[2]), "=f"(c[3])
        : "r"(a0), "r"(a1), "r"(a2), "r"(a3), "r"(b0), "r"(b1),
          "f"(0.0f), "f"(0.0f), "f"(0.0f), "f"(0.0f));
}
__device__ __forceinline__ unsigned smem_u32(const void* p) {
    return (unsigned)__cvta_generic_to_shared(p);
}
__device__ __forceinline__ void ldsm4(unsigned r[4], const __half* p) {
    unsigned a = smem_u32(p);
    asm volatile("ldmatrix.sync.aligned.m8n8.x4.shared.b16 {%0,%1,%2,%3}, [%4];"
                 : "=r"(r[0]), "=r"(r[1]), "=r"(r[2]), "=r"(r[3]) : "r"(a));
}
__device__ __forceinline__ void cp16(unsigned dst, const void* src) {
    asm volatile("cp.async.cg.shared.global [%0], [%1], 16;" :: "r"(dst), "l"(src));
}
__device__ __forceinline__ void cp_commit() {
    asm volatile("cp.async.commit_group;");
}
template<int N> __device__ __forceinline__ void cp_wait() {
    asm volatile("cp.async.wait_group %0;" :: "n"(N));
}

// ---------------------------------------------------------------------------
// Prologue: fp32 -> fp16 conversions + tiled weight transposes.
// ---------------------------------------------------------------------------
__global__ void convert_x_kernel(const float* __restrict__ x) {
    int i = blockIdx.x * blockDim.x + threadIdx.x;    // 1M float4
    float4 v = ((const float4*)x)[i];
    uint2 o;
    o.x = pack_h2(v.x, v.y);
    o.y = pack_h2(v.z, v.w);
    ((uint2*)g_x)[i] = o;
}

__global__ void convert_w_kernel(const float* __restrict__ Wq,
                                 const float* __restrict__ Wk,
                                 const float* __restrict__ Wv,
                                 const float* __restrict__ Wo) {
    __shared__ float tile[32][33];
    const int z  = blockIdx.z;
    const int tx = threadIdx.x;
    const int ty = threadIdx.y;
    if (z == 3) {
        const int c0 = blockIdx.y * 32;
        const int d0 = blockIdx.x * 32;
#pragma unroll
        for (int k = 0; k < 4; k++) {
            int r = ty + k * 8;
            tile[r][tx] = Wo[(size_t)(c0 + r) * DM + d0 + tx];
        }
        __syncthreads();
#pragma unroll
        for (int k = 0; k < 4; k++) {
            int rr = ty + k * 8;
            g_wo[(size_t)(d0 + rr) * DM + c0 + tx] = __float2half_rn(tile[tx][rr]);
        }
    } else {
        const float* W = (z == 0) ? Wq : (z == 1) ? Wk : Wv;
        __half* dst    = (z == 0) ? g_wq : (z == 1) ? g_wk : g_wv;
        const int h  = blockIdx.y >> 1;
        const int e0 = (blockIdx.y & 1) * 32;
        const int d0 = blockIdx.x * 32;
        const float* src = W + (size_t)h * DM * DH;
#pragma unroll
        for (int k = 0; k < 4; k++) {
            int r = ty + k * 8;
            tile[r][tx] = src[(size_t)(d0 + r) * DH + e0 + tx];
        }
        __syncthreads();
#pragma unroll
        for (int k = 0; k < 4; k++) {
            int rr = ty + k * 8;
            dst[(size_t)(h * DH + e0 + rr) * DM + d0 + tx] = __float2half_rn(tile[tx][rr]);
        }
    }
}

// ---------------------------------------------------------------------------
// GEMM geometry: BM=128, BN=128, BK=32 (fp16), 3-stage cp.async, ldmatrix.
// (R7 config — validated fastest)
// ---------------------------------------------------------------------------
constexpr int AS_LD = 40;            // halves per row (32 data + 8 pad)
constexpr int BS_LD = 40;
constexpr int A_ST  = 128 * AS_LD;
constexpr int B_ST  = 128 * BS_LD;
constexpr size_t GEMM_SMEM_BYTES = (size_t)3 * (A_ST + B_ST) * 2;  // 61,440

#define GEMM_ISSUE(Asrc_, Bsrc_, kt_, st_) do {                                   \
    const int kb_ = (kt_) * 32;                                                   \
    __half* Ad_ = As + (st_) * A_ST;                                              \
    __half* Bd_ = Bs + (st_) * B_ST;                                              \
    int r_ = tid >> 1, c_ = (tid & 1) * 16;                                       \
    cp16(smem_u32(Ad_ + r_ * AS_LD + c_),                                         \
         (Asrc_) + (size_t)(m0 + r_) * DM + kb_ + c_);                            \
    cp16(smem_u32(Ad_ + r_ * AS_LD + c_ + 8),                                     \
         (Asrc_) + (size_t)(m0 + r_) * DM + kb_ + c_ + 8);                        \
    cp16(smem_u32(Bd_ + r_ * BS_LD + c_),                                         \
         (Bsrc_) + (size_t)(n0 + r_) * DM + kb_ + c_);                            \
    cp16(smem_u32(Bd_ + r_ * BS_LD + c_ + 8),                                     \
         (Bsrc_) + (size_t)(n0 + r_) * DM + kb_ + c_ + 8);                        \
} while (0)

#define GEMM_COMPUTE(st_) do {                                                    \
    const __half* Asr = As + (st_) * A_ST;                                        \
    const __half* Bsr = Bs + (st_) * B_ST;                                        \
    _Pragma("unroll")                                                             \
    for (int ck = 0; ck < 2; ck++) {                                              \
        unsigned a[4][4];                                                         \
        _Pragma("unroll")                                                         \
        for (int mt = 0; mt < 4; mt++)                                            \
            ldsm4(a[mt], Asr + (wm * 64 + mt * 16 + fa_r) * AS_LD                 \
                          + ck * 16 + fa_h);                                      \
        _Pragma("unroll")                                                         \
        for (int c2 = 0; c2 < 2; c2++) {                                          \
            unsigned bf[4];                                                       \
            ldsm4(bf, Bsr + (wn * 32 + c2 * 16 + fb_r) * BS_LD                    \
                       + ck * 16 + fb_h);                                         \
            _Pragma("unroll")                                                     \
            for (int mt = 0; mt < 4; mt++) {                                      \
                mma_f16(acc[mt][2 * c2],     a[mt][0], a[mt][1], a[mt][2],        \
                        a[mt][3], bf[0], bf[1]);                                  \
                mma_f16(acc[mt][2 * c2 + 1], a[mt][0], a[mt][1], a[mt][2],        \
                        a[mt][3], bf[2], bf[3]);                                  \
            }                                                                     \
        }                                                                         \
    }                                                                             \
} while (0)

// ---------------------------------------------------------------------------
// Kernel 1: fused QKV projection (fp16). Q pre-scaled; V stored transposed.
// ---------------------------------------------------------------------------
__global__ __launch_bounds__(256, 2) void qkv_gemm_tc(
    const float* __restrict__ bq, const float* __restrict__ bk,
    const float* __restrict__ bv)
{
    extern __shared__ __half sg[];
    __half* As = sg;
    __half* Bs = sg + 3 * A_ST;

    const int pz = blockIdx.z;
    const __half* gw  = (pz == 0) ? g_wq : (pz == 1) ? g_wk : g_wv;
    const float* bias = (pz == 0) ? bq : (pz == 1) ? bk : bv;

    const int n0 = blockIdx.x * 128;
    const int m0 = blockIdx.y * 128;
    const int tid  = threadIdx.x;
    const int wid  = tid >> 5;
    const int lane = tid & 31;
    const int wm = wid >> 2;
    const int wn = wid & 3;
    const int g  = lane >> 2;
    const int t  = lane & 3;
    const int fa_r = lane & 15;
    const int fa_h = ((lane >> 4) & 1) * 8;
    const int fb_r = ((lane >> 4) & 1) * 8 + (lane & 7);
    const int fb_h = ((lane >> 3) & 1) * 8;

    float acc[4][4][4] = {};

    GEMM_ISSUE(g_x, gw, 0, 0); cp_commit();
    GEMM_ISSUE(g_x, gw, 1, 1); cp_commit();

    constexpr int NKT = DM / 32;   // 32
    for (int kt = 0; kt < NKT; ++kt) {
        cp_wait<1>();
        __syncthreads();
        if (kt + 2 < NKT) GEMM_ISSUE(g_x, gw, kt + 2, (kt + 2) % 3);
        cp_commit();
        GEMM_COMPUTE(kt % 3);
    }

#pragma unroll
    for (int mt = 0; mt < 4; mt++) {
#pragma unroll
        for (int nt = 0; nt < 4; nt++) {
            int mg = m0 + wm * 64 + mt * 16 + g;
            int c  = n0 + wn * 32 + nt * 8 + t * 2;
            int h  = c >> 6;
            int e  = c & 63;
            float b0 = bias[c], b1 = bias[c + 1];
#pragma unroll
            for (int rr = 0; rr < 2; rr++) {
                int mgr = mg + rr * 8;
                int bb = mgr >> 11;
                int ss = mgr & (SEQ - 1);
                float v0 = acc[mt][nt][rr * 2 + 0] + b0;
                float v1 = acc[mt][nt][rr * 2 + 1] + b1;
                if (pz == 0) {
                    v0 *= QSCALE; v1 *= QSCALE;
                    size_t idx = ((((size_t)bb * NH + h) * SEQ + ss) * DH + e);
                    *(unsigned*)&g_q[idx] = pack_h2(v0, v1);
                } else if (pz == 1) {
                    size_t idx = ((((size_t)bb * NH + h) * SEQ + ss) * DH + e);
                    *(unsigned*)&g_k[idx] = pack_h2(v0, v1);
                } else {
                    size_t base = (((size_t)bb * NH + h) * DH + e) * SEQ + ss;
                    g_v[base]       = __float2half_rn(v0);
                    g_v[base + SEQ] = __float2half_rn(v1);
                }
            }
        }
    }
}

// ---------------------------------------------------------------------------
// Kernel 2: causal flash attention — 128 q-rows per CTA (256 thr, 8 warps,
// 2 CTAs/SM): halves K/V L2 traffic per unit work vs 64-row tiles.
// XOR-swizzled K/V/Q (LD=64); 3-stage cp.async, prefetch distance 2,
// wait_group<1>. Grid bh-fastest (uniform waves). No max-tracking;
// P = ex2.f16x2; l via ones-column MMA.
// ---------------------------------------------------------------------------
constexpr int QK_ST = 64 * 64;   // halves per swizzled 64x64 tile
constexpr size_t SMEM_FLASH_BYTES = (size_t)(8 * QK_ST) * 2;  // 2Q + 3K + 3V = 65,536

// swizzled address (halves): row, chunk = 16B unit in [0,8)
#define SWZ(base_, row_, chunk_) ((base_) + (row_) * 64 + (((chunk_) ^ ((row_) & 7)) * 8))

#define FLASH_ISSUE_KV(j_, st_) do {                                             \
    const __half* kp_ = Kg + (size_t)((j_) * 64 + kk) * DH + grp * 16;           \
    const __half* vp_ = Vg + (size_t)kk * SEQ + (j_) * 64 + grp * 16;            \
    __half* kd_ = Ks + (st_) * QK_ST;                                            \
    __half* vd_ = Vt + (st_) * QK_ST;                                            \
    _Pragma("unroll")                                                            \
    for (int i_ = 0; i_ < 2; i_++) {                                             \
        int c_ = grp * 2 + i_;                                                   \
        cp16(smem_u32(SWZ(kd_, kk, c_)), kp_ + i_ * 8);                          \
        cp16(smem_u32(SWZ(vd_, kk, c_)), vp_ + i_ * 8);                          \
    }                                                                            \
} while (0)

__global__ __launch_bounds__(256, 2) void flash_attn_tc()
{
    extern __shared__ __half smh[];
    __half* Qs = smh;                 // [128x64] swizzled
    __half* Ks = Qs + 2 * QK_ST;      // 3 stages, rows=key, cols=e
    __half* Vt = Ks + 3 * QK_ST;      // 3 stages, rows=e, cols=key

    const int bhid  = blockIdx.x;                        // bh fastest
    const int itile = (int)(gridDim.y - 1) - blockIdx.y; // heavy q-tiles first
    const int q0    = itile * 128;
    const __half* Qg = g_q + (size_t)bhid * SEQ * DH;
    const __half* Kg = g_k + (size_t)bhid * SEQ * DH;
    const __half* Vg = g_v + (size_t)bhid * DH * SEQ;   // transposed [e][s]

    const int tid  = threadIdx.x;
    const int wid  = tid >> 5;           // 0..7
    const int lane = tid & 31;
    const int g  = lane >> 2;
    const int t  = lane & 3;
    const int r0 = wid * 16 + g;         // local q row (0..127)
    const int r1 = r0 + 8;
    const int kk  = tid & 63;
    const int grp = tid >> 6;            // 0..3
    const int fa_r = lane & 15;
    const int fa_c = (lane >> 4) & 1;
    const int fb_r = ((lane >> 4) & 1) * 8 + (lane & 7);
    const int fb_c = (lane >> 3) & 1;
    const unsigned ones_b = (g == 0) ? 0x3C003C00u : 0u;   // fp16 ones column

    const int jmax = 2 * itile + 1;      // key tiles 0..jmax

    // prologue: prefetch tiles 0 and 1
    FLASH_ISSUE_KV(0, 0);
    cp_commit();
    FLASH_ISSUE_KV(1, 1);
    cp_commit();

    // plain-store Q (fp16, pre-scaled) into swizzled tile (128 rows)
    {
        int q  = tid >> 1;
        const __half* src = Qg + (size_t)(q0 + q) * DH + (tid & 1) * 32;
#pragma unroll
        for (int i = 0; i < 4; i++) {
            int c = (tid & 1) * 4 + i;
            *(uint4*)SWZ(Qs, q, c) = ((const uint4*)src)[i];
        }
    }
    __syncthreads();   // Q visible (plain STS)

    // hoist Q fragments via ldmatrix (swizzled rows)
    unsigned qf[4][4];
#pragma unroll
    for (int ec = 0; ec < 4; ec++)
        ldsm4(qf[ec], SWZ(Qs, wid * 16 + fa_r, 2 * ec + fa_c));

    float o[8][4] = {};
    float oL[4] = {};

    for (int j = 0; j <= jmax; ++j) {
        if (j < jmax) cp_wait<1>(); else cp_wait<0>();
        __syncthreads();
        if (j + 2 <= jmax) { FLASH_ISSUE_KV(j + 2, (j + 2) % 3); cp_commit(); }

        const __half* Kst = Ks + (j % 3) * QK_ST;
        const __half* Vst = Vt + (j % 3) * QK_ST;

        // ---- Phase A: S = Q K^T ----
        float s[8][4];
#pragma unroll
        for (int ec = 0; ec < 4; ec++) {
#pragma unroll
            for (int c2 = 0; c2 < 4; c2++) {
                unsigned bf[4];
                ldsm4(bf, SWZ(Kst, c2 * 16 + fb_r, 2 * ec + fb_c));
                if (ec == 0) {
                    mma_f16_zero(s[2 * c2],     qf[0][0], qf[0][1], qf[0][2],
                                 qf[0][3], bf[0], bf[1]);
                    mma_f16_zero(s[2 * c2 + 1], qf[0][0], qf[0][1], qf[0][2],
                                 qf[0][3], bf[2], bf[3]);
                } else {
                    mma_f16(s[2 * c2],     qf[ec][0], qf[ec][1], qf[ec][2],
                            qf[ec][3], bf[0], bf[1]);
                    mma_f16(s[2 * c2 + 1], qf[ec][0], qf[ec][1], qf[ec][2],
                            qf[ec][3], bf[2], bf[3]);
                }
            }
        }

        // ---- mask (last two key tiles straddle the diagonal) ----
        if (j >= 2 * itile) {
            const int k0 = j * 64;
#pragma unroll
            for (int nt = 0; nt < 8; nt++) {
#pragma unroll
                for (int cc = 0; cc < 2; cc++) {
                    int kg = k0 + nt * 8 + t * 2 + cc;
                    if (kg > q0 + r0) s[nt][cc]     = -3.0e4f;
                    if (kg > q0 + r1) s[nt][2 + cc] = -3.0e4f;
                }
            }
        }

        // ---- Phase C: P = ex2h2(pack(s)); O += P V; l via ones ----
#pragma unroll
        for (int kc = 0; kc < 4; kc++) {
            unsigned a0 = ex2h2(pack_h2(s[2 * kc][0],     s[2 * kc][1]));
            unsigned a1 = ex2h2(pack_h2(s[2 * kc][2],     s[2 * kc][3]));
            unsigned a2 = ex2h2(pack_h2(s[2 * kc + 1][0], s[2 * kc + 1][1]));
            unsigned a3 = ex2h2(pack_h2(s[2 * kc + 1][2], s[2 * kc + 1][3]));
#pragma unroll
            for (int c2 = 0; c2 < 4; c2++) {
                unsigned bf[4];
                ldsm4(bf, SWZ(Vst, c2 * 16 + fb_r, 2 * kc + fb_c));
                mma_f16(o[2 * c2],     a0, a1, a2, a3, bf[0], bf[1]);
                mma_f16(o[2 * c2 + 1], a0, a1, a2, a3, bf[2], bf[3]);
            }
            mma_f16(oL, a0, a1, a2, a3, ones_b, ones_b);
        }
    }

    // ---- epilogue: z[b, q, h, e] = fp16(o / l), l from ones-column ----
    const int bb = bhid >> 4;
    const int h  = bhid & 15;
    float lr0 = __shfl_sync(0xFFFFFFFFu, oL[0], lane & 0x1C);
    float lr1 = __shfl_sync(0xFFFFFFFFu, oL[2], lane & 0x1C);
    const float li0 = 1.0f / lr0;
    const float li1 = 1.0f / lr1;
#pragma unroll
    for (int nt = 0; nt < 8; nt++) {
        const int e = nt * 8 + t * 2;
        size_t i0 = (((size_t)bb * SEQ + (q0 + r0)) * NH + h) * DH + e;
        size_t i1 = (((size_t)bb * SEQ + (q0 + r1)) * NH + h) * DH + e;
        *(unsigned*)&g_z[i0] = pack_h2(o[nt][0] * li0, o[nt][1] * li0);
        *(unsigned*)&g_z[i1] = pack_h2(o[nt][2] * li1, o[nt][3] * li1);
    }
}

// ---------------------------------------------------------------------------
// Kernel 3: output projection.
// ---------------------------------------------------------------------------
__global__ __launch_bounds__(256, 2) void out_gemm_tc(
    const float* __restrict__ bO, float* __restrict__ out)
{
    extern __shared__ __half sg[];
    __half* As = sg;
    __half* Bs = sg + 3 * A_ST;

    const int n0 = blockIdx.x * 128;
    const int m0 = blockIdx.y * 128;
    const int tid  = threadIdx.x;
    const int wid  = tid >> 5;
    const int lane = tid & 31;
    const int wm = wid >> 2;
    const int wn = wid & 3;
    const int g  = lane >> 2;
    const int t  = lane & 3;
    const int fa_r = lane & 15;
    const int fa_h = ((lane >> 4) & 1) * 8;
    const int fb_r = ((lane >> 4) & 1) * 8 + (lane & 7);
    const int fb_h = ((lane >> 3) & 1) * 8;

    float acc[4][4][4] = {};

    GEMM_ISSUE(g_z, g_wo, 0, 0); cp_commit();
    GEMM_ISSUE(g_z, g_wo, 1, 1); cp_commit();

    constexpr int NKT = DM / 32;   // 32
    for (int kt = 0; kt < NKT; ++kt) {
        cp_wait<1>();
        __syncthreads();
        if (kt + 2 < NKT) GEMM_ISSUE(g_z, g_wo, kt + 2, (kt + 2) % 3);
        cp_commit();
        GEMM_COMPUTE(kt % 3);
    }

#pragma unroll
    for (int mt = 0; mt < 4; mt++) {
#pragma unroll
        for (int nt = 0; nt < 4; nt++) {
            int mg = m0 + wm * 64 + mt * 16 + g;
            int c  = n0 + wn * 32 + nt * 8 + t * 2;
            float b0 = bO[c], b1 = bO[c + 1];
#pragma unroll
            for (int rr = 0; rr < 2; rr++) {
                float2 w;
                w.x = acc[mt][nt][rr * 2 + 0] + b0;
                w.y = acc[mt][nt][rr * 2 + 1] + b1;
                *(float2*)(out + (size_t)(mg + rr * 8) * DM + c) = w;
            }
        }
    }
}

// ---------------------------------------------------------------------------
// Launch
// ---------------------------------------------------------------------------
extern "C" void kernel_launch(void* const* d_in, const int* in_sizes, int n_in,
                              void* d_out, int out_size)
{
    const float* x  = (const float*)d_in[0];
    const float* Wq = (const float*)d_in[1];
    const float* bq = (const float*)d_in[2];
    const float* Wk = (const float*)d_in[3];
    const float* bk = (const float*)d_in[4];
    const float* Wv = (const float*)d_in[5];
    const float* bv = (const float*)d_in[6];
    const float* Wo = (const float*)d_in[7];
    const float* bo = (const float*)d_in[8];
    float* out = (float*)d_out;

    cudaFuncSetAttribute(qkv_gemm_tc,
                         cudaFuncAttributeMaxDynamicSharedMemorySize,
                         (int)GEMM_SMEM_BYTES);
    cudaFuncSetAttribute(out_gemm_tc,
                         cudaFuncAttributeMaxDynamicSharedMemorySize,
                         (int)GEMM_SMEM_BYTES);
    cudaFuncSetAttribute(flash_attn_tc,
                         cudaFuncAttributeMaxDynamicSharedMemorySize,
                         (int)SMEM_FLASH_BYTES);

    convert_x_kernel<<<(MROWS * DM / 4) / 256, 256>>>(x);
    convert_w_kernel<<<dim3(32, 32, 4), dim3(32, 8)>>>(Wq, Wk, Wv, Wo);

    dim3 g1(DM / 128, MROWS / 128, 3);   // (8, 32, 3)
    qkv_gemm_tc<<<g1, 256, GEMM_SMEM_BYTES>>>(bq, bk, bv);

    dim3 g2(B_ * NH, SEQ / 128);          // (32 bh, 16 q-tiles) — bh fastest
    flash_attn_tc<<<g2, 256, SMEM_FLASH_BYTES>>>();

    dim3 g3(DM / 128, MROWS / 128);       // (8, 32)
    out_gemm_tc<<<g3, 256, GEMM_SMEM_BYTES>>>(bo, out);
}